// round 2
// baseline (speedup 1.0000x reference)
#include <cuda_runtime.h>

#define TB        32
#define NTHREADS  256
#define OBS_DIM   464

typedef unsigned long long ull;

// ---------- f32x2 helpers (sm_103a packed-FMA path) ----------
__device__ __forceinline__ ull pk2(float lo, float hi) {
    ull r; asm("mov.b64 %0, {%1, %2};" : "=l"(r) : "f"(lo), "f"(hi)); return r;
}
__device__ __forceinline__ float2 upk2(ull v) {
    float2 f; asm("mov.b64 {%0, %1}, %2;" : "=f"(f.x), "=f"(f.y) : "l"(v)); return f;
}
__device__ __forceinline__ void fma2(ull& d, ull a, ull b) {
    asm("fma.rn.f32x2 %0, %1, %2, %0;" : "+l"(d) : "l"(a), "l"(b));
}

// tanh(x) = 1 - 2/(exp(2x)+1): ~1e-6 rel err, MUFU-pipe (ex2 + rcp)
__device__ __forceinline__ float ftanh(float x) {
    float e = __expf(x + x);
    return 1.0f - __fdividef(2.0f, e + 1.0f);
}

// ---------- accumulator helpers (4 rows x 4 f32x2-pairs = 4x8 cols) ----------
__device__ __forceinline__ void acc_zero(ull acc[4][4]) {
#pragma unroll
    for (int r = 0; r < 4; ++r) {
        acc[r][0] = 0ULL; acc[r][1] = 0ULL; acc[r][2] = 0ULL; acc[r][3] = 0ULL;
    }
}
__device__ __forceinline__ void acc_init_bias(ull acc[4][4], const float* __restrict__ b,
                                              int c0, int c1) {
    float4 b0 = *reinterpret_cast<const float4*>(b + c0);
    float4 b1 = *reinterpret_cast<const float4*>(b + c1);
    ull p0 = pk2(b0.x, b0.y), p1 = pk2(b0.z, b0.w);
    ull p2 = pk2(b1.x, b1.y), p3 = pk2(b1.z, b1.w);
#pragma unroll
    for (int r = 0; r < 4; ++r) {
        acc[r][0] = p0; acc[r][1] = p1; acc[r][2] = p2; acc[r][3] = p3;
    }
}
__device__ __forceinline__ void row_store_raw(float* dst, const ull a[4], int c0, int c1) {
    float2 t0 = upk2(a[0]), t1 = upk2(a[1]), t2 = upk2(a[2]), t3 = upk2(a[3]);
    *reinterpret_cast<float4*>(dst + c0) = make_float4(t0.x, t0.y, t1.x, t1.y);
    *reinterpret_cast<float4*>(dst + c1) = make_float4(t2.x, t2.y, t3.x, t3.y);
}
__device__ __forceinline__ void row_store_tanh(float* dst, const ull a[4], int c0, int c1) {
    float2 t0 = upk2(a[0]), t1 = upk2(a[1]), t2 = upk2(a[2]), t3 = upk2(a[3]);
    *reinterpret_cast<float4*>(dst + c0) =
        make_float4(ftanh(t0.x), ftanh(t0.y), ftanh(t1.x), ftanh(t1.y));
    *reinterpret_cast<float4*>(dst + c1) =
        make_float4(ftanh(t2.x), ftanh(t2.y), ftanh(t3.x), ftanh(t3.y));
}

// ---------- GEMM engine: [32 rows x 256 cols] += A[32 x K] * W[K x 256] ----------
// A in smem (row stride 256), W streamed from global through a 32x256 smem tile.
__device__ __forceinline__ void gemm_pass(
    ull acc[4][4],
    const float* __restrict__ sA, int rowbase,
    const float* __restrict__ Wsrc, int ktiles,
    float* __restrict__ sW, int tid, int c0, int c1)
{
    for (int t = 0; t < ktiles; ++t) {
        __syncthreads();  // previous tile compute done before overwrite
        {
            const float4* src = reinterpret_cast<const float4*>(Wsrc + (size_t)t * 8192);
            float4* dst = reinterpret_cast<float4*>(sW);
#pragma unroll
            for (int i = 0; i < 8; ++i) dst[i * 256 + tid] = src[i * 256 + tid];
        }
        __syncthreads();
        const float* sAt = sA + t * 32;
#pragma unroll 8
        for (int k = 0; k < 32; ++k) {
            float4 w0 = *reinterpret_cast<const float4*>(sW + k * 256 + c0);
            float4 w1 = *reinterpret_cast<const float4*>(sW + k * 256 + c1);
            ull wa = pk2(w0.x, w0.y), wb = pk2(w0.z, w0.w);
            ull wc = pk2(w1.x, w1.y), wd = pk2(w1.z, w1.w);
#pragma unroll
            for (int r = 0; r < 4; ++r) {
                float a = sAt[(rowbase + r) * 256 + k];
                ull a2 = pk2(a, a);
                fma2(acc[r][0], a2, wa);
                fma2(acc[r][1], a2, wb);
                fma2(acc[r][2], a2, wc);
                fma2(acc[r][3], a2, wd);
            }
        }
    }
}

// ---------- entity embedding: 8 cols of tanh(f @ W + b) ----------
template<int F>
__device__ __forceinline__ void emb8(float e[8],
    const float* __restrict__ fp, const float* __restrict__ Wg,
    ull bb0, ull bb1, ull bb2, ull bb3, int c0, int c1)
{
    ull a0 = bb0, a1 = bb1, a2 = bb2, a3 = bb3;
#pragma unroll
    for (int j = 0; j < F; ++j) {
        float fv = fp[j];
        ull f2 = pk2(fv, fv);
        float4 w0 = *reinterpret_cast<const float4*>(Wg + j * 256 + c0);
        float4 w1 = *reinterpret_cast<const float4*>(Wg + j * 256 + c1);
        fma2(a0, f2, pk2(w0.x, w0.y)); fma2(a1, f2, pk2(w0.z, w0.w));
        fma2(a2, f2, pk2(w1.x, w1.y)); fma2(a3, f2, pk2(w1.z, w1.w));
    }
    float2 t;
    t = upk2(a0); e[0] = ftanh(t.x); e[1] = ftanh(t.y);
    t = upk2(a1); e[2] = ftanh(t.x); e[3] = ftanh(t.y);
    t = upk2(a2); e[4] = ftanh(t.x); e[5] = ftanh(t.y);
    t = upk2(a3); e[6] = ftanh(t.x); e[7] = ftanh(t.y);
}

// ---------- per-warp attention pool for one (row, group) ----------
// feats: smem entity features for this row+group; Wg/bg: smem weights;
// qv: smem q vector in, vi out (same 256-float slot); sBeta: 16-float warp scratch.
template<int N, int F>
__device__ __forceinline__ void attend_group(
    const float* __restrict__ feats,
    const float* __restrict__ Wg, const float* __restrict__ bg,
    float* __restrict__ qv, float* __restrict__ sBeta,
    int c0, int c1)
{
    float4 q0 = *reinterpret_cast<const float4*>(qv + c0);
    float4 q1 = *reinterpret_cast<const float4*>(qv + c1);
    float4 b0 = *reinterpret_cast<const float4*>(bg + c0);
    float4 b1 = *reinterpret_cast<const float4*>(bg + c1);
    ull bb0 = pk2(b0.x, b0.y), bb1 = pk2(b0.z, b0.w);
    ull bb2 = pk2(b1.x, b1.y), bb3 = pk2(b1.z, b1.w);

    // pass 1: beta[n] = q . emb[n]
#pragma unroll 1
    for (int n = 0; n < N; ++n) {
        float e[8];
        emb8<F>(e, feats + n * F, Wg, bb0, bb1, bb2, bb3, c0, c1);
        float p = q0.x * e[0] + q0.y * e[1] + q0.z * e[2] + q0.w * e[3]
                + q1.x * e[4] + q1.y * e[5] + q1.z * e[6] + q1.w * e[7];
#pragma unroll
        for (int s = 16; s > 0; s >>= 1) p += __shfl_xor_sync(0xffffffffu, p, s);
        sBeta[n] = p;  // all lanes write the same value (benign)
    }
    // softmax stats
    float m = -3.4e38f;
#pragma unroll 1
    for (int n = 0; n < N; ++n) m = fmaxf(m, sBeta[n]);
    float s = 0.0f;
#pragma unroll 1
    for (int n = 0; n < N; ++n) s += __expf(sBeta[n] - m);
    float inv = __fdividef(1.0f, s);

    // pass 2: vi = sum_n alpha[n] * emb[n]  (recompute emb)
    float v0 = 0, v1 = 0, v2 = 0, v3 = 0, v4 = 0, v5 = 0, v6 = 0, v7 = 0;
#pragma unroll 1
    for (int n = 0; n < N; ++n) {
        float e[8];
        emb8<F>(e, feats + n * F, Wg, bb0, bb1, bb2, bb3, c0, c1);
        float al = __expf(sBeta[n] - m) * inv;
        v0 = fmaf(al, e[0], v0); v1 = fmaf(al, e[1], v1);
        v2 = fmaf(al, e[2], v2); v3 = fmaf(al, e[3], v3);
        v4 = fmaf(al, e[4], v4); v5 = fmaf(al, e[5], v5);
        v6 = fmaf(al, e[6], v6); v7 = fmaf(al, e[7], v7);
    }
    *reinterpret_cast<float4*>(qv + c0) = make_float4(v0, v1, v2, v3);
    *reinterpret_cast<float4*>(qv + c1) = make_float4(v4, v5, v6, v7);
}

// Shared memory layout (floats):
//  sIn   @ 0      : 32*464 = 14848   (staged input rows; reused as h after attention)
//  sEmb  @ 14848  : 32*256 =  8192   (emb_self; reused as gi)
//  sQ    @ 23040  : 32*768 = 24576   (q_other|q_box|q_ramp -> vi_other|vi_box|vi_ramp)
//  sW    @ 47616  : 9728            (GEMM W k-tile (8192) / entity weights+biases (9728))
//  sBeta @ 57344  : 128             (per-warp beta scratch)
// total 57472 floats = 229888 bytes
#define SMEM_FLOATS 57472
#define SMEM_BYTES  (SMEM_FLOATS * 4)

__global__ void __launch_bounds__(NTHREADS, 1)
obs_encoder_kernel(
    const float* __restrict__ gIn,
    const float* __restrict__ W_self,  const float* __restrict__ b_self,
    const float* __restrict__ W_other, const float* __restrict__ b_other,
    const float* __restrict__ W_box,   const float* __restrict__ b_box,
    const float* __restrict__ W_ramp,  const float* __restrict__ b_ramp,
    const float* __restrict__ corr_other, const float* __restrict__ corr_box,
    const float* __restrict__ corr_ramp,
    const float* __restrict__ W_fc, const float* __restrict__ b_fc,
    const float* __restrict__ W_e1, const float* __restrict__ b_e1,
    const float* __restrict__ W_e2, const float* __restrict__ b_e2,
    float* __restrict__ out)
{
    extern __shared__ float sm[];
    float* sIn  = sm;
    float* sEmb = sm + 14848;
    float* sQ   = sm + 23040;
    float* sW   = sm + 47616;
    float* sBetaAll = sm + 57344;

    const int tid  = threadIdx.x;
    const int lane = tid & 31;
    const int rg   = tid >> 5;          // warp id = row group
    const int rowbase = rg * 4;         // this warp's 4 local rows
    const int c0 = lane * 4;            // cols c0..c0+3
    const int c1 = c0 + 128;            // cols c1..c1+3
    const size_t row0 = (size_t)blockIdx.x * TB;

    // ---- phase 0: stage 32 input rows (contiguous 14848 floats) ----
    {
        const float2* src = reinterpret_cast<const float2*>(gIn + row0 * OBS_DIM);
        float2* dst = reinterpret_cast<float2*>(sIn);
#pragma unroll
        for (int i = 0; i < 29; ++i) dst[i * 256 + tid] = src[i * 256 + tid];
    }
    __syncthreads();

    // ---- phase 1: emb_self = tanh(self_in @ W_self + b_self), K=10 ----
    {
        ull acc[4][4];
        acc_init_bias(acc, b_self, c0, c1);
#pragma unroll
        for (int k = 0; k < 10; ++k) {
            float4 w0 = *reinterpret_cast<const float4*>(W_self + k * 256 + c0);
            float4 w1 = *reinterpret_cast<const float4*>(W_self + k * 256 + c1);
            ull wa = pk2(w0.x, w0.y), wb = pk2(w0.z, w0.w);
            ull wc = pk2(w1.x, w1.y), wd = pk2(w1.z, w1.w);
#pragma unroll
            for (int r = 0; r < 4; ++r) {
                float a = sIn[(rowbase + r) * OBS_DIM + k];
                ull a2 = pk2(a, a);
                fma2(acc[r][0], a2, wa); fma2(acc[r][1], a2, wb);
                fma2(acc[r][2], a2, wc); fma2(acc[r][3], a2, wd);
            }
        }
#pragma unroll
        for (int r = 0; r < 4; ++r)
            row_store_tanh(sEmb + (rowbase + r) * 256, acc[r], c0, c1);
    }
    // (gemm_pass leading __syncthreads orders sEmb writes)

    // ---- phase 2: q_g = emb_self @ corr_g (raw), gi = tanh(emb_self @ W_fc + b_fc) ----
    {
        ull acc[4][4];
        acc_zero(acc);
        gemm_pass(acc, sEmb, rowbase, corr_other, 8, sW, tid, c0, c1);
#pragma unroll
        for (int r = 0; r < 4; ++r)
            row_store_raw(sQ + (rowbase + r) * 256, acc[r], c0, c1);

        acc_zero(acc);
        gemm_pass(acc, sEmb, rowbase, corr_box, 8, sW, tid, c0, c1);
#pragma unroll
        for (int r = 0; r < 4; ++r)
            row_store_raw(sQ + 8192 + (rowbase + r) * 256, acc[r], c0, c1);

        acc_zero(acc);
        gemm_pass(acc, sEmb, rowbase, corr_ramp, 8, sW, tid, c0, c1);
#pragma unroll
        for (int r = 0; r < 4; ++r)
            row_store_raw(sQ + 16384 + (rowbase + r) * 256, acc[r], c0, c1);

        acc_init_bias(acc, b_fc, c0, c1);
        gemm_pass(acc, sEmb, rowbase, W_fc, 8, sW, tid, c0, c1);
        __syncthreads();  // all reads of emb_self done -> safe to overwrite with gi
#pragma unroll
        for (int r = 0; r < 4; ++r)
            row_store_tanh(sEmb + (rowbase + r) * 256, acc[r], c0, c1);
    }

    // ---- phase 3: attention pools (warp-private rows) ----
    {
        // stage entity weights + biases into sW (GEMM reads of sW are behind the sync above)
        for (int i = tid; i < 2560; i += NTHREADS) sW[i]        = W_other[i];
        sW[2560 + tid] = b_other[tid];
        for (int i = tid; i < 3328; i += NTHREADS) sW[2816 + i] = W_box[i];
        sW[6144 + tid] = b_box[tid];
        for (int i = tid; i < 3072; i += NTHREADS) sW[6400 + i] = W_ramp[i];
        sW[9472 + tid] = b_ramp[tid];
        __syncthreads();

        float* sBeta = sBetaAll + rg * 16;
#pragma unroll 1
        for (int r = 0; r < 4; ++r) {
            const int row = rowbase + r;
            const float* inrow = sIn + row * OBS_DIM;
            attend_group<15, 10>(inrow + 10,  sW + 0,    sW + 2560,
                                 sQ + row * 256,           sBeta, c0, c1);
            attend_group<16, 13>(inrow + 160, sW + 2816, sW + 6144,
                                 sQ + 8192 + row * 256,    sBeta, c0, c1);
            attend_group<8, 12>( inrow + 368, sW + 6400, sW + 9472,
                                 sQ + 16384 + row * 256,   sBeta, c0, c1);
        }
    }

    // ---- phase 4: h = tanh(cat @ W_e1 + b_e1), cat = [gi | vi_o | vi_b | vi_r] ----
    {
        ull acc[4][4];
        acc_init_bias(acc, b_e1, c0, c1);
        gemm_pass(acc, sEmb,        rowbase, W_e1,           8, sW, tid, c0, c1);
        gemm_pass(acc, sQ,          rowbase, W_e1 + 65536,   8, sW, tid, c0, c1);
        gemm_pass(acc, sQ + 8192,   rowbase, W_e1 + 131072,  8, sW, tid, c0, c1);
        gemm_pass(acc, sQ + 16384,  rowbase, W_e1 + 196608,  8, sW, tid, c0, c1);
        // sIn (inputs) no longer read by anyone past this point -> reuse as h
#pragma unroll
        for (int r = 0; r < 4; ++r)
            row_store_tanh(sIn + (rowbase + r) * 256, acc[r], c0, c1);
    }

    // ---- phase 5: out = tanh(h @ W_e2 + b_e2) ----
    {
        ull acc[4][4];
        acc_init_bias(acc, b_e2, c0, c1);
        gemm_pass(acc, sIn, rowbase, W_e2, 8, sW, tid, c0, c1);  // leading sync orders h
#pragma unroll
        for (int r = 0; r < 4; ++r) {
            float* dst = out + (row0 + rowbase + r) * 256;
            row_store_tanh(dst, acc[r], c0, c1);
        }
    }
}

extern "C" void kernel_launch(void* const* d_in, const int* in_sizes, int n_in,
                              void* d_out, int out_size) {
    const float* inputs     = (const float*)d_in[0];
    const float* W_self     = (const float*)d_in[1];
    const float* b_self     = (const float*)d_in[2];
    const float* W_other    = (const float*)d_in[3];
    const float* b_other    = (const float*)d_in[4];
    const float* W_box      = (const float*)d_in[5];
    const float* b_box      = (const float*)d_in[6];
    const float* W_ramp     = (const float*)d_in[7];
    const float* b_ramp     = (const float*)d_in[8];
    const float* corr_other = (const float*)d_in[9];
    const float* corr_box   = (const float*)d_in[10];
    const float* corr_ramp  = (const float*)d_in[11];
    const float* W_fc       = (const float*)d_in[12];
    const float* b_fc       = (const float*)d_in[13];
    const float* W_e1       = (const float*)d_in[14];
    const float* b_e1       = (const float*)d_in[15];
    const float* W_e2       = (const float*)d_in[16];
    const float* b_e2       = (const float*)d_in[17];
    float* out = (float*)d_out;

    const int B = in_sizes[0] / OBS_DIM;   // 32768
    const int nblocks = B / TB;            // 1024

    cudaFuncSetAttribute(obs_encoder_kernel,
                         cudaFuncAttributeMaxDynamicSharedMemorySize, SMEM_BYTES);

    obs_encoder_kernel<<<nblocks, NTHREADS, SMEM_BYTES>>>(
        inputs, W_self, b_self, W_other, b_other, W_box, b_box, W_ramp, b_ramp,
        corr_other, corr_box, corr_ramp, W_fc, b_fc, W_e1, b_e1, W_e2, b_e2, out);
}